// round 8
// baseline (speedup 1.0000x reference)
#include <cuda_runtime.h>
#include <cuda_fp16.h>
#include <mma.h>

using namespace nvcuda;

// Problem constants (B=2, C=32, X=96)
#define BATCH        2
#define XD           96
#define XSTRIDE      9216        // 96*96
#define CH_STRIDE    884736      // X^3
#define B_STRIDE     28311552    // 32 * X^3
#define CHUNKS_PER_B 13824       // 48 * 288  (288 = 9216/32)
#define GPB          296         // blocks per batch; grid = 592 = 4*148 (one wave at occ 4)
#define NWARPS       4
#define TILE_LD      72          // 64 voxels + 8 pad halves
#define GRID_TOTAL   (BATCH * GPB)

// Accumulators: zero at module load; fused finalize re-zeroes after reading,
// so every launch/replay sees zeros (deterministic).
__device__ float    g_A[BATCH][1024];
__device__ float    g_vol[BATCH][32];
__device__ float    g_sym;
__device__ unsigned g_done;

__global__ __launch_bounds__(128, 4) void main_kernel(
    const float* __restrict__ logits,
    const float* __restrict__ age,
    const float* __restrict__ wy,
    const float* __restrict__ wo,
    const float* __restrict__ vmy,
    const float* __restrict__ vmo,
    const float* __restrict__ vsy,
    const float* __restrict__ vso,
    const float* __restrict__ prior,
    float* __restrict__ out)
{
    __shared__ __align__(256) __half tiles[NWARPS][32 * TILE_LD];
    __shared__ __align__(256) __half ones_b[256];   // 16x16 col-major, col 0 = 1.0
    __shared__ unsigned s_last;

    const int tid  = threadIdx.x;
    const int warp = tid >> 5;
    const int lane = tid & 31;
    const int b    = blockIdx.x / GPB;
    const int blk  = blockIdx.x % GPB;
    const unsigned wg    = blk * NWARPS + warp;
    const unsigned wstep = GPB * NWARPS;          // 1184 warps per batch

    // ones block: element (k,n) at ones_b[n*16+k]; column 0 = 1.0
    #pragma unroll
    for (int i = tid; i < 256; i += 128)
        ones_b[i] = (i < 16) ? __float2half(1.0f) : __float2half(0.0f);
    __syncthreads();

    const float* Lb = logits + b * B_STRIDE;
    __half* tile = tiles[warp];

    wmma::fragment<wmma::accumulator, 16, 16, 16, float> acc[2][2];
    wmma::fragment<wmma::accumulator, 16, 16, 16, float> accv[2];
    #pragma unroll
    for (int i = 0; i < 2; i++) {
        wmma::fill_fragment(accv[i], 0.0f);
        #pragma unroll
        for (int j = 0; j < 2; j++)
            wmma::fill_fragment(acc[i][j], 0.0f);
    }
    wmma::fragment<wmma::matrix_b, 16, 16, 16, __half, wmma::col_major> fbv;
    wmma::load_matrix_sync(fbv, ones_b, 16);

    float symacc = 0.f;

    for (unsigned chunk = wg; chunk < CHUNKS_PER_B; chunk += wstep) {
        const unsigned x = chunk / 288u;
        const unsigned s = (chunk - x * 288u) * 32u + lane;
        const float* L1 = Lb + x * XSTRIDE + s;
        const float* L2 = Lb + (XD - 1 - x) * XSTRIDE + s;

        // h[c] = (exp(l1[c]), exp(l2[c])) in half2. No max-subtraction:
        // logits ~N(0,1); half range (max 65504) cannot overflow (needs logit>11).
        half2 h[32];
        #pragma unroll
        for (int c = 0; c < 32; c++) {
            float l1 = L1[c * CH_STRIDE];
            float l2 = L2[c * CH_STRIDE];
            h[c] = h2exp(__floats2half2_rn(l1, l2));
        }

        // component-wise tree sum -> (sum1, sum2), then rcp -> normalize
        {
            half2 t[16];
            #pragma unroll
            for (int i = 0; i < 16; i++) t[i] = __hadd2(h[2 * i], h[2 * i + 1]);
            #pragma unroll
            for (int i = 0; i < 8; i++)  t[i] = __hadd2(t[i], t[i + 8]);
            #pragma unroll
            for (int i = 0; i < 4; i++)  t[i] = __hadd2(t[i], t[i + 4]);
            t[0] = __hadd2(t[0], t[2]);
            t[1] = __hadd2(t[1], t[3]);
            half2 inv = h2rcp(__hadd2(t[0], t[1]));
            #pragma unroll
            for (int c = 0; c < 32; c++) h[c] = __hmul2(h[c], inv);
        }

        // symmetry: pair (c, c+16): |p1[c]-p2[c+16]| + |p2[c]-p1[c+16]|
        {
            half2 sa = __floats2half2_rn(0.f, 0.f);
            #pragma unroll
            for (int i = 0; i < 16; i++) {
                half2 bs = __lowhigh2highlow(h[i + 16]);
                sa = __hadd2(sa, __habs2(__hsub2(h[i], bs)));
            }
            symacc += __low2float(sa) + __high2float(sa);
        }

        // stage fp16 tile: [channel][voxel-pair] packed half2 (pure K-permutation)
        #pragma unroll
        for (int c = 0; c < 32; c++)
            *reinterpret_cast<half2*>(tile + c * TILE_LD + 2 * lane) = h[c];
        __syncwarp();

        // ---- Gram + volume accumulate on tensor pipe ----
        #pragma unroll
        for (int kk = 0; kk < 4; kk++) {
            wmma::fragment<wmma::matrix_a, 16, 16, 16, __half, wmma::row_major> fa0, fa1;
            wmma::fragment<wmma::matrix_b, 16, 16, 16, __half, wmma::col_major> fb0, fb1;
            wmma::load_matrix_sync(fa0, tile + kk * 16, TILE_LD);
            wmma::load_matrix_sync(fa1, tile + 16 * TILE_LD + kk * 16, TILE_LD);
            wmma::load_matrix_sync(fb0, tile + kk * 16, TILE_LD);
            wmma::load_matrix_sync(fb1, tile + 16 * TILE_LD + kk * 16, TILE_LD);
            wmma::mma_sync(acc[0][0], fa0, fb0, acc[0][0]);
            wmma::mma_sync(acc[0][1], fa0, fb1, acc[0][1]);
            wmma::mma_sync(acc[1][0], fa1, fb0, acc[1][0]);
            wmma::mma_sync(acc[1][1], fa1, fb1, acc[1][1]);
            wmma::mma_sync(accv[0], fa0, fbv, accv[0]);
            wmma::mma_sync(accv[1], fa1, fbv, accv[1]);
        }
        __syncwarp();
    }

    // ---- flush Gram: fragments -> smem (fp32, ld=32) -> global atomics ----
    float* ftile = reinterpret_cast<float*>(tile);
    #pragma unroll
    for (int ci = 0; ci < 2; ci++)
        #pragma unroll
        for (int di = 0; di < 2; di++)
            wmma::store_matrix_sync(ftile + ci * 16 * 32 + di * 16, acc[ci][di], 32,
                                    wmma::mem_row_major);
    __syncwarp();
    #pragma unroll 4
    for (int r = 0; r < 32; r++)
        atomicAdd(&g_A[b][r * 32 + lane], ftile[r * 32 + lane]);
    __syncwarp();

    // ---- flush volume (column 0 of accv holds row sums) ----
    wmma::store_matrix_sync(ftile,       accv[0], 16, wmma::mem_row_major);
    wmma::store_matrix_sync(ftile + 256, accv[1], 16, wmma::mem_row_major);
    __syncwarp();
    {
        float v = (lane < 16) ? ftile[lane * 16] : ftile[256 + (lane - 16) * 16];
        atomicAdd(&g_vol[b][lane], v);
    }

    // ---- flush sym ----
    #pragma unroll
    for (int o = 16; o > 0; o >>= 1) symacc += __shfl_xor_sync(0xFFFFFFFF, symacc, o);
    if (lane == 0) atomicAdd(&g_sym, symacc);

    // ================= fused finalize: last block to finish =================
    __threadfence();
    __syncthreads();
    if (tid == 0)
        s_last = (atomicAdd(&g_done, 1u) == GRID_TOTAL - 1) ? 1u : 0u;
    __syncthreads();
    if (s_last && tid < 32) {
        __threadfence();
        const int c = lane;
        const float a0 = fminf(fmaxf(age[0] * 0.01f, 0.f), 1.f);
        const float a1 = fminf(fmaxf(age[1] * 0.01f, 0.f), 1.f);

        float aw[32], pr[32];
        float rsum = 0.f, psum = 0.f;
        #pragma unroll
        for (int d = 0; d < 32; d++) {
            float wyv = wy[c * 32 + d], wov = wo[c * 32 + d];
            float w0 = (1.f - a0) * wyv + a0 * wov;
            float w1 = (1.f - a1) * wyv + a1 * wov;
            float v = (d == c) ? 0.f
                               : 0.5f * (g_A[0][c * 32 + d] * w0 + g_A[1][c * 32 + d] * w1);
            aw[d] = v; rsum += v;
            float pv = (d == c) ? 0.f : prior[c * 32 + d];
            pr[d] = pv; psum += pv;
        }
        const float rinv = 1.f / fmaxf(rsum, 1e-8f);
        const float pinv = 1.f / fmaxf(psum, 1e-8f);
        float part = 0.f;
        #pragma unroll
        for (int d = 0; d < 32; d++) part += fabsf(aw[d] * rinv - pr[d] * pinv);
        #pragma unroll
        for (int o = 16; o > 0; o >>= 1) part += __shfl_xor_sync(0xFFFFFFFF, part, o);
        const float loss_adj = part * (1.f / 1024.f);

        // volume smooth-L1
        float vpart = 0.f;
        {
            float mean = (1.f - a0) * vmy[c] + a0 * vmo[c];
            float std  = (1.f - a0) * vsy[c] + a0 * vso[c];
            float xx = (g_vol[0][c] - mean) / (std + 1e-6f);
            float ax = fabsf(xx);
            vpart += (ax < 1.f) ? 0.5f * xx * xx : ax - 0.5f;
        }
        {
            float mean = (1.f - a1) * vmy[c] + a1 * vmo[c];
            float std  = (1.f - a1) * vsy[c] + a1 * vso[c];
            float xx = (g_vol[1][c] - mean) / (std + 1e-6f);
            float ax = fabsf(xx);
            vpart += (ax < 1.f) ? 0.5f * xx * xx : ax - 0.5f;
        }
        #pragma unroll
        for (int o = 16; o > 0; o >>= 1) vpart += __shfl_xor_sync(0xFFFFFFFF, vpart, o);
        const float loss_vol = vpart * (1.f / 64.f);

        // symmetry (x2: each flip-pair counted once per direction)
        const float loss_sym = 2.f * g_sym / 56623104.f;   // B*C*X^3

        if (c == 0)
            out[0] = 0.15f * loss_adj + 0.2f * loss_vol + 0.05f * loss_sym;

        // re-zero accumulators + counter for the next launch/replay
        __syncwarp();
        #pragma unroll
        for (int d = 0; d < 32; d++) { g_A[0][c * 32 + d] = 0.f; g_A[1][c * 32 + d] = 0.f; }
        g_vol[0][c] = 0.f;
        g_vol[1][c] = 0.f;
        if (c == 0) { g_sym = 0.f; g_done = 0u; }
    }
}

extern "C" void kernel_launch(void* const* d_in, const int* in_sizes, int n_in,
                              void* d_out, int out_size) {
    const float* logits = (const float*)d_in[0];
    const float* age    = (const float*)d_in[1];
    const float* wy     = (const float*)d_in[2];
    const float* wo     = (const float*)d_in[3];
    const float* vmy    = (const float*)d_in[4];
    const float* vmo    = (const float*)d_in[5];
    const float* vsy    = (const float*)d_in[6];
    const float* vso    = (const float*)d_in[7];
    const float* prior  = (const float*)d_in[8];
    float* out = (float*)d_out;

    main_kernel<<<GRID_TOTAL, 128>>>(logits, age, wy, wo, vmy, vmo, vsy, vso, prior, out);
}

// round 9
// speedup vs baseline: 1.3232x; 1.3232x over previous
#include <cuda_runtime.h>
#include <cuda_fp16.h>
#include <mma.h>

using namespace nvcuda;

// Problem constants (B=2, C=32, X=96)
#define BATCH        2
#define XD           96
#define XSTRIDE      9216        // 96*96
#define CH_STRIDE    884736      // X^3
#define B_STRIDE     28311552    // 32 * X^3
#define CHUNKS_PER_B 13824       // 48 * 288  (288 = 9216/32)
#define GPB          222         // blocks per batch; grid = 444 = 3*148 (one wave at occ 3)
#define NWARPS       4
#define TILE_LD      72          // 64 voxels + 8 pad halves
#define GRID_TOTAL   (BATCH * GPB)

// Accumulators: zero at module load; fused finalize re-zeroes after reading,
// so every launch/replay sees zeros (deterministic).
__device__ float    g_A[BATCH][1024];
__device__ float    g_vol[BATCH][32];
__device__ float    g_sym;
__device__ unsigned g_done;

__global__ __launch_bounds__(128, 3) void main_kernel(
    const float* __restrict__ logits,
    const float* __restrict__ age,
    const float* __restrict__ wy,
    const float* __restrict__ wo,
    const float* __restrict__ vmy,
    const float* __restrict__ vmo,
    const float* __restrict__ vsy,
    const float* __restrict__ vso,
    const float* __restrict__ prior,
    float* __restrict__ out)
{
    __shared__ __align__(256) __half tiles[NWARPS][32 * TILE_LD];
    __shared__ __align__(256) __half ones_b[256];   // 16x16 col-major, col 0 = 1.0
    __shared__ unsigned s_last;

    const int tid  = threadIdx.x;
    const int warp = tid >> 5;
    const int lane = tid & 31;
    const int b    = blockIdx.x / GPB;
    const int blk  = blockIdx.x % GPB;
    const unsigned wg    = blk * NWARPS + warp;
    const unsigned wstep = GPB * NWARPS;          // 888 warps per batch

    // ones block: element (k,n) at ones_b[n*16+k]; column 0 = 1.0
    #pragma unroll
    for (int i = tid; i < 256; i += 128)
        ones_b[i] = (i < 16) ? __float2half(1.0f) : __float2half(0.0f);
    __syncthreads();

    const float* Lb = logits + b * B_STRIDE;
    __half* tile = tiles[warp];

    wmma::fragment<wmma::accumulator, 16, 16, 16, float> acc[2][2];
    wmma::fragment<wmma::accumulator, 16, 16, 16, float> accv[2];
    #pragma unroll
    for (int i = 0; i < 2; i++) {
        wmma::fill_fragment(accv[i], 0.0f);
        #pragma unroll
        for (int j = 0; j < 2; j++)
            wmma::fill_fragment(acc[i][j], 0.0f);
    }
    wmma::fragment<wmma::matrix_b, 16, 16, 16, __half, wmma::col_major> fbv;
    wmma::load_matrix_sync(fbv, ones_b, 16);

    float symacc = 0.f;

    for (unsigned chunk = wg; chunk < CHUNKS_PER_B; chunk += wstep) {
        const unsigned x = chunk / 288u;
        const unsigned s = (chunk - x * 288u) * 32u + lane;
        const float* L1 = Lb + x * XSTRIDE + s;
        const float* L2 = Lb + (XD - 1 - x) * XSTRIDE + s;

        // h[c] = (exp(l1[c]), exp(l2[c])) in half2. No max-subtraction:
        // logits ~N(0,1); half range (max 65504) cannot overflow (needs logit>11).
        half2 h[32];
        #pragma unroll
        for (int c = 0; c < 32; c++) {
            float l1 = L1[c * CH_STRIDE];
            float l2 = L2[c * CH_STRIDE];
            h[c] = h2exp(__floats2half2_rn(l1, l2));
        }

        // component-wise tree sum -> (sum1, sum2), then rcp -> normalize
        {
            half2 t[16];
            #pragma unroll
            for (int i = 0; i < 16; i++) t[i] = __hadd2(h[2 * i], h[2 * i + 1]);
            #pragma unroll
            for (int i = 0; i < 8; i++)  t[i] = __hadd2(t[i], t[i + 8]);
            #pragma unroll
            for (int i = 0; i < 4; i++)  t[i] = __hadd2(t[i], t[i + 4]);
            t[0] = __hadd2(t[0], t[2]);
            t[1] = __hadd2(t[1], t[3]);
            half2 inv = h2rcp(__hadd2(t[0], t[1]));
            #pragma unroll
            for (int c = 0; c < 32; c++) h[c] = __hmul2(h[c], inv);
        }

        // symmetry: pair (c, c+16): |p1[c]-p2[c+16]| + |p2[c]-p1[c+16]|
        {
            half2 sa = __floats2half2_rn(0.f, 0.f);
            #pragma unroll
            for (int i = 0; i < 16; i++) {
                half2 bs = __lowhigh2highlow(h[i + 16]);
                sa = __hadd2(sa, __habs2(__hsub2(h[i], bs)));
            }
            symacc += __low2float(sa) + __high2float(sa);
        }

        // stage fp16 tile: [channel][voxel-pair] packed half2 (pure K-permutation)
        #pragma unroll
        for (int c = 0; c < 32; c++)
            *reinterpret_cast<half2*>(tile + c * TILE_LD + 2 * lane) = h[c];
        __syncwarp();

        // ---- Gram + volume accumulate on tensor pipe ----
        #pragma unroll
        for (int kk = 0; kk < 4; kk++) {
            wmma::fragment<wmma::matrix_a, 16, 16, 16, __half, wmma::row_major> fa0, fa1;
            wmma::fragment<wmma::matrix_b, 16, 16, 16, __half, wmma::col_major> fb0, fb1;
            wmma::load_matrix_sync(fa0, tile + kk * 16, TILE_LD);
            wmma::load_matrix_sync(fa1, tile + 16 * TILE_LD + kk * 16, TILE_LD);
            wmma::load_matrix_sync(fb0, tile + kk * 16, TILE_LD);
            wmma::load_matrix_sync(fb1, tile + 16 * TILE_LD + kk * 16, TILE_LD);
            wmma::mma_sync(acc[0][0], fa0, fb0, acc[0][0]);
            wmma::mma_sync(acc[0][1], fa0, fb1, acc[0][1]);
            wmma::mma_sync(acc[1][0], fa1, fb0, acc[1][0]);
            wmma::mma_sync(acc[1][1], fa1, fb1, acc[1][1]);
            wmma::mma_sync(accv[0], fa0, fbv, accv[0]);
            wmma::mma_sync(accv[1], fa1, fbv, accv[1]);
        }
        __syncwarp();
    }

    // ---- flush Gram: fragments -> smem (fp32, ld=32) -> global atomics ----
    float* ftile = reinterpret_cast<float*>(tile);
    #pragma unroll
    for (int ci = 0; ci < 2; ci++)
        #pragma unroll
        for (int di = 0; di < 2; di++)
            wmma::store_matrix_sync(ftile + ci * 16 * 32 + di * 16, acc[ci][di], 32,
                                    wmma::mem_row_major);
    __syncwarp();
    #pragma unroll 4
    for (int r = 0; r < 32; r++)
        atomicAdd(&g_A[b][r * 32 + lane], ftile[r * 32 + lane]);
    __syncwarp();

    // ---- flush volume (column 0 of accv holds row sums) ----
    wmma::store_matrix_sync(ftile,       accv[0], 16, wmma::mem_row_major);
    wmma::store_matrix_sync(ftile + 256, accv[1], 16, wmma::mem_row_major);
    __syncwarp();
    {
        float v = (lane < 16) ? ftile[lane * 16] : ftile[256 + (lane - 16) * 16];
        atomicAdd(&g_vol[b][lane], v);
    }

    // ---- flush sym ----
    #pragma unroll
    for (int o = 16; o > 0; o >>= 1) symacc += __shfl_xor_sync(0xFFFFFFFF, symacc, o);
    if (lane == 0) atomicAdd(&g_sym, symacc);

    // ================= fused finalize: last block to finish =================
    __threadfence();
    __syncthreads();
    if (tid == 0)
        s_last = (atomicAdd(&g_done, 1u) == GRID_TOTAL - 1) ? 1u : 0u;
    __syncthreads();
    if (s_last && tid < 32) {
        __threadfence();
        const int c = lane;
        const float a0 = fminf(fmaxf(age[0] * 0.01f, 0.f), 1.f);
        const float a1 = fminf(fmaxf(age[1] * 0.01f, 0.f), 1.f);

        float aw[32], pr[32];
        float rsum = 0.f, psum = 0.f;
        #pragma unroll
        for (int d = 0; d < 32; d++) {
            float wyv = wy[c * 32 + d], wov = wo[c * 32 + d];
            float w0 = (1.f - a0) * wyv + a0 * wov;
            float w1 = (1.f - a1) * wyv + a1 * wov;
            float v = (d == c) ? 0.f
                               : 0.5f * (g_A[0][c * 32 + d] * w0 + g_A[1][c * 32 + d] * w1);
            aw[d] = v; rsum += v;
            float pv = (d == c) ? 0.f : prior[c * 32 + d];
            pr[d] = pv; psum += pv;
        }
        const float rinv = 1.f / fmaxf(rsum, 1e-8f);
        const float pinv = 1.f / fmaxf(psum, 1e-8f);
        float part = 0.f;
        #pragma unroll
        for (int d = 0; d < 32; d++) part += fabsf(aw[d] * rinv - pr[d] * pinv);
        #pragma unroll
        for (int o = 16; o > 0; o >>= 1) part += __shfl_xor_sync(0xFFFFFFFF, part, o);
        const float loss_adj = part * (1.f / 1024.f);

        // volume smooth-L1
        float vpart = 0.f;
        {
            float mean = (1.f - a0) * vmy[c] + a0 * vmo[c];
            float std  = (1.f - a0) * vsy[c] + a0 * vso[c];
            float xx = (g_vol[0][c] - mean) / (std + 1e-6f);
            float ax = fabsf(xx);
            vpart += (ax < 1.f) ? 0.5f * xx * xx : ax - 0.5f;
        }
        {
            float mean = (1.f - a1) * vmy[c] + a1 * vmo[c];
            float std  = (1.f - a1) * vsy[c] + a1 * vso[c];
            float xx = (g_vol[1][c] - mean) / (std + 1e-6f);
            float ax = fabsf(xx);
            vpart += (ax < 1.f) ? 0.5f * xx * xx : ax - 0.5f;
        }
        #pragma unroll
        for (int o = 16; o > 0; o >>= 1) vpart += __shfl_xor_sync(0xFFFFFFFF, vpart, o);
        const float loss_vol = vpart * (1.f / 64.f);

        // symmetry (x2: each flip-pair counted once per direction)
        const float loss_sym = 2.f * g_sym / 56623104.f;   // B*C*X^3

        if (c == 0)
            out[0] = 0.15f * loss_adj + 0.2f * loss_vol + 0.05f * loss_sym;

        // re-zero accumulators + counter for the next launch/replay
        __syncwarp();
        #pragma unroll
        for (int d = 0; d < 32; d++) { g_A[0][c * 32 + d] = 0.f; g_A[1][c * 32 + d] = 0.f; }
        g_vol[0][c] = 0.f;
        g_vol[1][c] = 0.f;
        if (c == 0) { g_sym = 0.f; g_done = 0u; }
    }
}

extern "C" void kernel_launch(void* const* d_in, const int* in_sizes, int n_in,
                              void* d_out, int out_size) {
    const float* logits = (const float*)d_in[0];
    const float* age    = (const float*)d_in[1];
    const float* wy     = (const float*)d_in[2];
    const float* wo     = (const float*)d_in[3];
    const float* vmy    = (const float*)d_in[4];
    const float* vmo    = (const float*)d_in[5];
    const float* vsy    = (const float*)d_in[6];
    const float* vso    = (const float*)d_in[7];
    const float* prior  = (const float*)d_in[8];
    float* out = (float*)d_out;

    main_kernel<<<GRID_TOTAL, 128>>>(logits, age, wy, wo, vmy, vmo, vsy, vso, prior, out);
}

// round 11
// speedup vs baseline: 1.5246x; 1.1522x over previous
#include <cuda_runtime.h>
#include <cuda_fp16.h>
#include <mma.h>

using namespace nvcuda;

// Problem constants (B=2, C=32, X=96)
#define BATCH        2
#define XD           96
#define XSTRIDE      9216        // 96*96
#define CH_STRIDE    884736      // X^3
#define B_STRIDE     28311552    // 32 * X^3
#define CHUNKS_PER_B 13824       // 48 * 288  (288 = 9216/32)
#define GPB          444         // blocks per batch; grid = 888 = 6*148 (one wave at occ 6)
#define NWARPS       2
#define TILE_LD      72          // 64 voxels + 8 pad halves (fp16 tile, overlaid on stage)
#define STAGE_BYTES  8192        // 64 rows * 128B of staged logits per warp per chunk
#define GRID_TOTAL   (BATCH * GPB)

// Accumulators: zero at module load; fused finalize re-zeroes after reading,
// so every launch/replay sees zeros (deterministic).
__device__ float    g_A[BATCH][1024];
__device__ float    g_vol[BATCH][32];
__device__ float    g_sym;
__device__ unsigned g_done;

__device__ __forceinline__ void cp_async16(void* smem_dst, const void* gmem_src) {
    unsigned saddr = (unsigned)__cvta_generic_to_shared(smem_dst);
    asm volatile("cp.async.cg.shared.global [%0], [%1], 16;\n"
                 :: "r"(saddr), "l"(gmem_src));
}
__device__ __forceinline__ void cp_commit() {
    asm volatile("cp.async.commit_group;\n");
}
template <int N>
__device__ __forceinline__ void cp_wait() {
    asm volatile("cp.async.wait_group %0;\n" :: "n"(N));
}

// Prefetch one chunk (64 rows x 128B) into a stage buffer. Always commits a
// group (possibly empty) so wait_group counting stays consistent.
__device__ __forceinline__ void prefetch_chunk(const float* __restrict__ Lb,
                                               unsigned chunk, char* stage,
                                               int lane, bool valid) {
    if (valid) {
        const unsigned x     = chunk / 288u;
        const unsigned sbase = (chunk - x * 288u) * 32u;
        const float* P1 = Lb + x * XSTRIDE + sbase;
        const float* P2 = Lb + (XD - 1 - x) * XSTRIDE + sbase;
        const int sub = lane >> 3;          // 0..3  (row group)
        const int off = (lane & 7) * 16;    // byte offset within 128B row
        #pragma unroll
        for (int k = 0; k < 8; k++) {
            int c = k * 4 + sub;
            cp_async16(stage + c * 128 + off,
                       (const char*)(P1 + c * CH_STRIDE) + off);
        }
        #pragma unroll
        for (int k = 0; k < 8; k++) {
            int c = k * 4 + sub;
            cp_async16(stage + (32 + c) * 128 + off,
                       (const char*)(P2 + c * CH_STRIDE) + off);
        }
    }
    cp_commit();
}

__global__ __launch_bounds__(64, 6) void main_kernel(
    const float* __restrict__ logits,
    const float* __restrict__ age,
    const float* __restrict__ wy,
    const float* __restrict__ wo,
    const float* __restrict__ vmy,
    const float* __restrict__ vmo,
    const float* __restrict__ vsy,
    const float* __restrict__ vso,
    const float* __restrict__ prior,
    float* __restrict__ out)
{
    __shared__ __align__(256) char stages[2][NWARPS][STAGE_BYTES];
    __shared__ __align__(256) __half ones_b[256];   // 16x16 col-major, col 0 = 1.0
    __shared__ unsigned s_last;

    const int tid  = threadIdx.x;
    const int warp = tid >> 5;
    const int lane = tid & 31;
    const int b    = blockIdx.x / GPB;
    const int blk  = blockIdx.x % GPB;
    const unsigned wg    = blk * NWARPS + warp;
    const unsigned wstep = GPB * NWARPS;          // 888 warps per batch

    // ones block: element (k,n) at ones_b[n*16+k]; column 0 = 1.0
    #pragma unroll
    for (int i = tid; i < 256; i += 64)
        ones_b[i] = (i < 16) ? __float2half(1.0f) : __float2half(0.0f);
    __syncthreads();

    const float* Lb = logits + b * B_STRIDE;

    wmma::fragment<wmma::accumulator, 16, 16, 16, float> acc[2][2];
    wmma::fragment<wmma::accumulator, 16, 16, 16, float> accv[2];
    #pragma unroll
    for (int i = 0; i < 2; i++) {
        wmma::fill_fragment(accv[i], 0.0f);
        #pragma unroll
        for (int j = 0; j < 2; j++)
            wmma::fill_fragment(acc[i][j], 0.0f);
    }
    wmma::fragment<wmma::matrix_b, 16, 16, 16, __half, wmma::col_major> fbv;
    wmma::load_matrix_sync(fbv, ones_b, 16);

    float symacc = 0.f;

    // ---- pipeline prologue: stage chunk(i) and chunk(i+wstep) ----
    prefetch_chunk(Lb, wg,          stages[0][warp], lane, wg < CHUNKS_PER_B);
    prefetch_chunk(Lb, wg + wstep,  stages[1][warp], lane, wg + wstep < CHUNKS_PER_B);

    unsigned parity = 0;
    for (unsigned chunk = wg; chunk < CHUNKS_PER_B; chunk += wstep) {
        cp_wait<1>();          // chunk's own stage group complete
        __syncwarp();

        char*  stage = stages[parity][warp];
        const float* st = reinterpret_cast<const float*>(stage);
        __half* tile = reinterpret_cast<__half*>(stage);

        // softmax over 32 channels for voxel pair (l1 from rows 0..31, l2 rows 32..63).
        // No max-subtraction: logits ~N(0,1); h2exp cannot overflow half (needs >11).
        half2 h[32];
        #pragma unroll
        for (int c = 0; c < 32; c++)
            h[c] = h2exp(__floats2half2_rn(st[c * 32 + lane], st[(32 + c) * 32 + lane]));

        {
            half2 t[16];
            #pragma unroll
            for (int i = 0; i < 16; i++) t[i] = __hadd2(h[2 * i], h[2 * i + 1]);
            #pragma unroll
            for (int i = 0; i < 8; i++)  t[i] = __hadd2(t[i], t[i + 8]);
            #pragma unroll
            for (int i = 0; i < 4; i++)  t[i] = __hadd2(t[i], t[i + 4]);
            t[0] = __hadd2(t[0], t[2]);
            t[1] = __hadd2(t[1], t[3]);
            half2 inv = h2rcp(__hadd2(t[0], t[1]));
            #pragma unroll
            for (int c = 0; c < 32; c++) h[c] = __hmul2(h[c], inv);
        }

        // symmetry: pair (c, c+16): |p1[c]-p2[c+16]| + |p2[c]-p1[c+16]|
        {
            half2 sa = __floats2half2_rn(0.f, 0.f);
            #pragma unroll
            for (int i = 0; i < 16; i++) {
                half2 bs = __lowhigh2highlow(h[i + 16]);
                sa = __hadd2(sa, __habs2(__hsub2(h[i], bs)));
            }
            symacc += __low2float(sa) + __high2float(sa);
        }

        __syncwarp();   // all lanes done reading staged logits before tile overwrite

        // stage fp16 tile into the SAME buffer (4608B <= 8192B); pure K-permutation
        #pragma unroll
        for (int c = 0; c < 32; c++)
            *reinterpret_cast<half2*>(tile + c * TILE_LD + 2 * lane) = h[c];
        __syncwarp();

        // ---- Gram + volume accumulate on tensor pipe ----
        #pragma unroll
        for (int kk = 0; kk < 4; kk++) {
            wmma::fragment<wmma::matrix_a, 16, 16, 16, __half, wmma::row_major> fa0, fa1;
            wmma::fragment<wmma::matrix_b, 16, 16, 16, __half, wmma::col_major> fb0, fb1;
            wmma::load_matrix_sync(fa0, tile + kk * 16, TILE_LD);
            wmma::load_matrix_sync(fa1, tile + 16 * TILE_LD + kk * 16, TILE_LD);
            wmma::load_matrix_sync(fb0, tile + kk * 16, TILE_LD);
            wmma::load_matrix_sync(fb1, tile + 16 * TILE_LD + kk * 16, TILE_LD);
            wmma::mma_sync(acc[0][0], fa0, fb0, acc[0][0]);
            wmma::mma_sync(acc[0][1], fa0, fb1, acc[0][1]);
            wmma::mma_sync(acc[1][0], fa1, fb0, acc[1][0]);
            wmma::mma_sync(acc[1][1], fa1, fb1, acc[1][1]);
            wmma::mma_sync(accv[0], fa0, fbv, accv[0]);
            wmma::mma_sync(accv[1], fa1, fbv, accv[1]);
        }
        // tile reads complete (ldsm results in registers) -> safe to re-stage this buffer
        prefetch_chunk(Lb, chunk + 2 * wstep, stage, lane,
                       chunk + 2 * wstep < CHUNKS_PER_B);
        parity ^= 1;
    }

    cp_wait<0>();     // drain any in-flight (possibly empty) groups before buffer reuse
    __syncwarp();

    // ---- flush Gram: fragments -> smem (fp32, ld=32) -> global atomics ----
    float* ftile = reinterpret_cast<float*>(stages[0][warp]);
    #pragma unroll
    for (int ci = 0; ci < 2; ci++)
        #pragma unroll
        for (int di = 0; di < 2; di++)
            wmma::store_matrix_sync(ftile + ci * 16 * 32 + di * 16, acc[ci][di], 32,
                                    wmma::mem_row_major);
    __syncwarp();
    #pragma unroll 4
    for (int r = 0; r < 32; r++)
        atomicAdd(&g_A[b][r * 32 + lane], ftile[r * 32 + lane]);
    __syncwarp();

    // ---- flush volume (column 0 of accv holds row sums) ----
    wmma::store_matrix_sync(ftile,       accv[0], 16, wmma::mem_row_major);
    wmma::store_matrix_sync(ftile + 256, accv[1], 16, wmma::mem_row_major);
    __syncwarp();
    {
        float v = (lane < 16) ? ftile[lane * 16] : ftile[256 + (lane - 16) * 16];
        atomicAdd(&g_vol[b][lane], v);
    }

    // ---- flush sym ----
    #pragma unroll
    for (int o = 16; o > 0; o >>= 1) symacc += __shfl_xor_sync(0xFFFFFFFF, symacc, o);
    if (lane == 0) atomicAdd(&g_sym, symacc);

    // ================= fused finalize: last block to finish =================
    __threadfence();
    __syncthreads();
    if (tid == 0)
        s_last = (atomicAdd(&g_done, 1u) == GRID_TOTAL - 1) ? 1u : 0u;
    __syncthreads();
    if (s_last && tid < 32) {
        __threadfence();
        const int c = lane;
        const float a0 = fminf(fmaxf(age[0] * 0.01f, 0.f), 1.f);
        const float a1 = fminf(fmaxf(age[1] * 0.01f, 0.f), 1.f);

        float aw[32], pr[32];
        float rsum = 0.f, psum = 0.f;
        #pragma unroll
        for (int d = 0; d < 32; d++) {
            float wyv = wy[c * 32 + d], wov = wo[c * 32 + d];
            float w0 = (1.f - a0) * wyv + a0 * wov;
            float w1 = (1.f - a1) * wyv + a1 * wov;
            float v = (d == c) ? 0.f
                               : 0.5f * (g_A[0][c * 32 + d] * w0 + g_A[1][c * 32 + d] * w1);
            aw[d] = v; rsum += v;
            float pv = (d == c) ? 0.f : prior[c * 32 + d];
            pr[d] = pv; psum += pv;
        }
        const float rinv = 1.f / fmaxf(rsum, 1e-8f);
        const float pinv = 1.f / fmaxf(psum, 1e-8f);
        float part = 0.f;
        #pragma unroll
        for (int d = 0; d < 32; d++) part += fabsf(aw[d] * rinv - pr[d] * pinv);
        #pragma unroll
        for (int o = 16; o > 0; o >>= 1) part += __shfl_xor_sync(0xFFFFFFFF, part, o);
        const float loss_adj = part * (1.f / 1024.f);

        // volume smooth-L1
        float vpart = 0.f;
        {
            float mean = (1.f - a0) * vmy[c] + a0 * vmo[c];
            float std  = (1.f - a0) * vsy[c] + a0 * vso[c];
            float xx = (g_vol[0][c] - mean) / (std + 1e-6f);
            float ax = fabsf(xx);
            vpart += (ax < 1.f) ? 0.5f * xx * xx : ax - 0.5f;
        }
        {
            float mean = (1.f - a1) * vmy[c] + a1 * vmo[c];
            float std  = (1.f - a1) * vsy[c] + a1 * vso[c];
            float xx = (g_vol[1][c] - mean) / (std + 1e-6f);
            float ax = fabsf(xx);
            vpart += (ax < 1.f) ? 0.5f * xx * xx : ax - 0.5f;
        }
        #pragma unroll
        for (int o = 16; o > 0; o >>= 1) vpart += __shfl_xor_sync(0xFFFFFFFF, vpart, o);
        const float loss_vol = vpart * (1.f / 64.f);

        // symmetry (x2: each flip-pair counted once per direction)
        const float loss_sym = 2.f * g_sym / 56623104.f;   // B*C*X^3

        if (c == 0)
            out[0] = 0.15f * loss_adj + 0.2f * loss_vol + 0.05f * loss_sym;

        // re-zero accumulators + counter for the next launch/replay
        __syncwarp();
        #pragma unroll
        for (int d = 0; d < 32; d++) { g_A[0][c * 32 + d] = 0.f; g_A[1][c * 32 + d] = 0.f; }
        g_vol[0][c] = 0.f;
        g_vol[1][c] = 0.f;
        if (c == 0) { g_sym = 0.f; g_done = 0u; }
    }
}

extern "C" void kernel_launch(void* const* d_in, const int* in_sizes, int n_in,
                              void* d_out, int out_size) {
    const float* logits = (const float*)d_in[0];
    const float* age    = (const float*)d_in[1];
    const float* wy     = (const float*)d_in[2];
    const float* wo     = (const float*)d_in[3];
    const float* vmy    = (const float*)d_in[4];
    const float* vmo    = (const float*)d_in[5];
    const float* vsy    = (const float*)d_in[6];
    const float* vso    = (const float*)d_in[7];
    const float* prior  = (const float*)d_in[8];
    float* out = (float*)d_out;

    main_kernel<<<GRID_TOTAL, 64>>>(logits, age, wy, wo, vmy, vmo, vsy, vso, prior, out);
}

// round 13
// speedup vs baseline: 1.5314x; 1.0044x over previous
#include <cuda_runtime.h>
#include <cuda_fp16.h>
#include <mma.h>

using namespace nvcuda;

// Problem constants (B=2, C=32, X=96)
#define BATCH        2
#define XD           96
#define XSTRIDE      9216        // 96*96
#define CH_STRIDE    884736      // X^3
#define B_STRIDE     28311552    // 32 * X^3
#define CHUNKS_PER_B 13824       // 48 * 288  (288 = 9216/32)
#define GPB          962         // blocks per batch; grid = 1924 = 13*148 (one wave at occ 13)
#define TILE_LD      72          // 64 voxels + 8 pad halves (fp16 tile, overlaid on stage)
#define STAGE_BYTES  8192        // 64 rows * 128B of staged logits per chunk
#define GRID_TOTAL   (BATCH * GPB)

// Accumulators: zero at module load; fused finalize re-zeroes after reading,
// so every launch/replay sees zeros (deterministic).
__device__ float    g_A[BATCH][1024];
__device__ float    g_vol[BATCH][32];
__device__ float    g_sym;
__device__ unsigned g_done;

__device__ __forceinline__ void cp_async16(void* smem_dst, const void* gmem_src) {
    unsigned saddr = (unsigned)__cvta_generic_to_shared(smem_dst);
    asm volatile("cp.async.cg.shared.global [%0], [%1], 16;\n"
                 :: "r"(saddr), "l"(gmem_src));
}
__device__ __forceinline__ void cp_commit() {
    asm volatile("cp.async.commit_group;\n");
}
template <int N>
__device__ __forceinline__ void cp_wait() {
    asm volatile("cp.async.wait_group %0;\n" :: "n"(N));
}

// Prefetch one chunk (64 rows x 128B) into a stage buffer. Always commits a
// group (possibly empty) so wait_group counting stays consistent.
__device__ __forceinline__ void prefetch_chunk(const float* __restrict__ Lb,
                                               unsigned chunk, char* stage,
                                               int lane, bool valid) {
    if (valid) {
        const unsigned x     = chunk / 288u;
        const unsigned sbase = (chunk - x * 288u) * 32u;
        const float* P1 = Lb + x * XSTRIDE + sbase;
        const float* P2 = Lb + (XD - 1 - x) * XSTRIDE + sbase;
        const int sub = lane >> 3;          // 0..3  (row group)
        const int off = (lane & 7) * 16;    // byte offset within 128B row
        #pragma unroll
        for (int k = 0; k < 8; k++) {
            int c = k * 4 + sub;
            cp_async16(stage + c * 128 + off,
                       (const char*)(P1 + c * CH_STRIDE) + off);
        }
        #pragma unroll
        for (int k = 0; k < 8; k++) {
            int c = k * 4 + sub;
            cp_async16(stage + (32 + c) * 128 + off,
                       (const char*)(P2 + c * CH_STRIDE) + off);
        }
    }
    cp_commit();
}

__global__ __launch_bounds__(32, 13) void main_kernel(
    const float* __restrict__ logits,
    const float* __restrict__ age,
    const float* __restrict__ wy,
    const float* __restrict__ wo,
    const float* __restrict__ vmy,
    const float* __restrict__ vmo,
    const float* __restrict__ vsy,
    const float* __restrict__ vso,
    const float* __restrict__ prior,
    float* __restrict__ out)
{
    __shared__ __align__(256) char stages[2][STAGE_BYTES];
    __shared__ __align__(256) __half ones_b[256];   // 16x16 col-major, col 0 = 1.0

    const int lane = threadIdx.x;                 // single warp per block
    const int b    = blockIdx.x / GPB;
    const int blk  = blockIdx.x % GPB;
    const unsigned wg    = blk;                   // warp id within batch
    const unsigned wstep = GPB;                   // 962 warps per batch

    // ones block: element (k,n) at ones_b[n*16+k]; column 0 = 1.0
    #pragma unroll
    for (int i = lane; i < 256; i += 32)
        ones_b[i] = (i < 16) ? __float2half(1.0f) : __float2half(0.0f);
    __syncwarp();

    const float* Lb = logits + b * B_STRIDE;

    wmma::fragment<wmma::accumulator, 16, 16, 16, float> acc[2][2];
    wmma::fragment<wmma::accumulator, 16, 16, 16, float> accv[2];
    #pragma unroll
    for (int i = 0; i < 2; i++) {
        wmma::fill_fragment(accv[i], 0.0f);
        #pragma unroll
        for (int j = 0; j < 2; j++)
            wmma::fill_fragment(acc[i][j], 0.0f);
    }
    wmma::fragment<wmma::matrix_b, 16, 16, 16, __half, wmma::col_major> fbv;
    wmma::load_matrix_sync(fbv, ones_b, 16);

    float symacc = 0.f;

    // ---- pipeline prologue: stage chunk(i) and chunk(i+wstep) ----
    prefetch_chunk(Lb, wg,          stages[0], lane, wg < CHUNKS_PER_B);
    prefetch_chunk(Lb, wg + wstep,  stages[1], lane, wg + wstep < CHUNKS_PER_B);

    unsigned parity = 0;
    for (unsigned chunk = wg; chunk < CHUNKS_PER_B; chunk += wstep) {
        cp_wait<1>();          // chunk's own stage group complete
        __syncwarp();

        char*  stage = stages[parity];
        const float* st = reinterpret_cast<const float*>(stage);
        __half* tile = reinterpret_cast<__half*>(stage);

        // softmax over 32 channels for voxel pair (l1 from rows 0..31, l2 rows 32..63).
        // No max-subtraction: logits ~N(0,1); h2exp cannot overflow half (needs >11).
        half2 h[32];
        #pragma unroll
        for (int c = 0; c < 32; c++)
            h[c] = h2exp(__floats2half2_rn(st[c * 32 + lane], st[(32 + c) * 32 + lane]));

        {
            half2 t[16];
            #pragma unroll
            for (int i = 0; i < 16; i++) t[i] = __hadd2(h[2 * i], h[2 * i + 1]);
            #pragma unroll
            for (int i = 0; i < 8; i++)  t[i] = __hadd2(t[i], t[i + 8]);
            #pragma unroll
            for (int i = 0; i < 4; i++)  t[i] = __hadd2(t[i], t[i + 4]);
            t[0] = __hadd2(t[0], t[2]);
            t[1] = __hadd2(t[1], t[3]);
            half2 inv = h2rcp(__hadd2(t[0], t[1]));
            #pragma unroll
            for (int c = 0; c < 32; c++) h[c] = __hmul2(h[c], inv);
        }

        // symmetry: pair (c, c+16): |p1[c]-p2[c+16]| + |p2[c]-p1[c+16]|
        {
            half2 sa = __floats2half2_rn(0.f, 0.f);
            #pragma unroll
            for (int i = 0; i < 16; i++) {
                half2 bs = __lowhigh2highlow(h[i + 16]);
                sa = __hadd2(sa, __habs2(__hsub2(h[i], bs)));
            }
            symacc += __low2float(sa) + __high2float(sa);
        }

        __syncwarp();   // all lanes done reading staged logits before tile overwrite

        // stage fp16 tile into the SAME buffer (4608B <= 8192B); pure K-permutation
        #pragma unroll
        for (int c = 0; c < 32; c++)
            *reinterpret_cast<half2*>(tile + c * TILE_LD + 2 * lane) = h[c];
        __syncwarp();

        // ---- Gram + volume accumulate on tensor pipe ----
        #pragma unroll
        for (int kk = 0; kk < 4; kk++) {
            wmma::fragment<wmma::matrix_a, 16, 16, 16, __half, wmma::row_major> fa0, fa1;
            wmma::fragment<wmma::matrix_b, 16, 16, 16, __half, wmma::col_major> fb0, fb1;
            wmma::load_matrix_sync(fa0, tile + kk * 16, TILE_LD);
            wmma::load_matrix_sync(fa1, tile + 16 * TILE_LD + kk * 16, TILE_LD);
            wmma::load_matrix_sync(fb0, tile + kk * 16, TILE_LD);
            wmma::load_matrix_sync(fb1, tile + 16 * TILE_LD + kk * 16, TILE_LD);
            wmma::mma_sync(acc[0][0], fa0, fb0, acc[0][0]);
            wmma::mma_sync(acc[0][1], fa0, fb1, acc[0][1]);
            wmma::mma_sync(acc[1][0], fa1, fb0, acc[1][0]);
            wmma::mma_sync(acc[1][1], fa1, fb1, acc[1][1]);
            wmma::mma_sync(accv[0], fa0, fbv, accv[0]);
            wmma::mma_sync(accv[1], fa1, fbv, accv[1]);
        }
        // tile reads complete (ldsm results in registers) -> safe to re-stage this buffer
        prefetch_chunk(Lb, chunk + 2 * wstep, stage, lane,
                       chunk + 2 * wstep < CHUNKS_PER_B);
        parity ^= 1;
    }

    cp_wait<0>();     // drain any in-flight (possibly empty) groups before buffer reuse
    __syncwarp();

    // ---- flush Gram: fragments -> smem (fp32, ld=32) -> global atomics ----
    float* ftile = reinterpret_cast<float*>(stages[0]);
    #pragma unroll
    for (int ci = 0; ci < 2; ci++)
        #pragma unroll
        for (int di = 0; di < 2; di++)
            wmma::store_matrix_sync(ftile + ci * 16 * 32 + di * 16, acc[ci][di], 32,
                                    wmma::mem_row_major);
    __syncwarp();
    #pragma unroll 4
    for (int r = 0; r < 32; r++)
        atomicAdd(&g_A[b][r * 32 + lane], ftile[r * 32 + lane]);
    __syncwarp();

    // ---- flush volume (column 0 of accv holds row sums) ----
    wmma::store_matrix_sync(ftile,       accv[0], 16, wmma::mem_row_major);
    wmma::store_matrix_sync(ftile + 256, accv[1], 16, wmma::mem_row_major);
    __syncwarp();
    {
        float v = (lane < 16) ? ftile[lane * 16] : ftile[256 + (lane - 16) * 16];
        atomicAdd(&g_vol[b][lane], v);
    }

    // ---- flush sym ----
    #pragma unroll
    for (int o = 16; o > 0; o >>= 1) symacc += __shfl_xor_sync(0xFFFFFFFF, symacc, o);
    if (lane == 0) atomicAdd(&g_sym, symacc);

    // ================= fused finalize: last block to finish =================
    __threadfence();
    __syncwarp();
    unsigned last = 0;
    if (lane == 0) last = (atomicAdd(&g_done, 1u) == GRID_TOTAL - 1) ? 1u : 0u;
    last = __shfl_sync(0xFFFFFFFF, last, 0);
    if (last) {
        __threadfence();
        const int c = lane;
        const float a0 = fminf(fmaxf(age[0] * 0.01f, 0.f), 1.f);
        const float a1 = fminf(fmaxf(age[1] * 0.01f, 0.f), 1.f);

        // batched row loads (float4, high MLP)
        float4 A0[8], A1[8], WY[8], WO[8], PR[8];
        {
            const float4* a0p = reinterpret_cast<const float4*>(&g_A[0][c * 32]);
            const float4* a1p = reinterpret_cast<const float4*>(&g_A[1][c * 32]);
            const float4* wyp = reinterpret_cast<const float4*>(wy + c * 32);
            const float4* wop = reinterpret_cast<const float4*>(wo + c * 32);
            const float4* prp = reinterpret_cast<const float4*>(prior + c * 32);
            #pragma unroll
            for (int q = 0; q < 8; q++) A0[q] = a0p[q];
            #pragma unroll
            for (int q = 0; q < 8; q++) A1[q] = a1p[q];
            #pragma unroll
            for (int q = 0; q < 8; q++) WY[q] = wyp[q];
            #pragma unroll
            for (int q = 0; q < 8; q++) WO[q] = wop[q];
            #pragma unroll
            for (int q = 0; q < 8; q++) PR[q] = prp[q];
        }
        const float* a0f = reinterpret_cast<const float*>(A0);
        const float* a1f = reinterpret_cast<const float*>(A1);
        const float* wyf = reinterpret_cast<const float*>(WY);
        const float* wof = reinterpret_cast<const float*>(WO);
        const float* prf = reinterpret_cast<const float*>(PR);

        float aw[32], pr[32];
        float rsum = 0.f, psum = 0.f;
        #pragma unroll
        for (int d = 0; d < 32; d++) {
            float w0 = (1.f - a0) * wyf[d] + a0 * wof[d];
            float w1 = (1.f - a1) * wyf[d] + a1 * wof[d];
            float v = (d == c) ? 0.f : 0.5f * (a0f[d] * w0 + a1f[d] * w1);
            aw[d] = v; rsum += v;
            float pv = (d == c) ? 0.f : prf[d];
            pr[d] = pv; psum += pv;
        }
        const float rinv = 1.f / fmaxf(rsum, 1e-8f);
        const float pinv = 1.f / fmaxf(psum, 1e-8f);
        float part = 0.f;
        #pragma unroll
        for (int d = 0; d < 32; d++) part += fabsf(aw[d] * rinv - pr[d] * pinv);
        #pragma unroll
        for (int o = 16; o > 0; o >>= 1) part += __shfl_xor_sync(0xFFFFFFFF, part, o);
        const float loss_adj = part * (1.f / 1024.f);

        // volume smooth-L1
        float vpart = 0.f;
        {
            float mean = (1.f - a0) * vmy[c] + a0 * vmo[c];
            float std  = (1.f - a0) * vsy[c] + a0 * vso[c];
            float xx = (g_vol[0][c] - mean) / (std + 1e-6f);
            float ax = fabsf(xx);
            vpart += (ax < 1.f) ? 0.5f * xx * xx : ax - 0.5f;
        }
        {
            float mean = (1.f - a1) * vmy[c] + a1 * vmo[c];
            float std  = (1.f - a1) * vsy[c] + a1 * vso[c];
            float xx = (g_vol[1][c] - mean) / (std + 1e-6f);
            float ax = fabsf(xx);
            vpart += (ax < 1.f) ? 0.5f * xx * xx : ax - 0.5f;
        }
        #pragma unroll
        for (int o = 16; o > 0; o >>= 1) vpart += __shfl_xor_sync(0xFFFFFFFF, vpart, o);
        const float loss_vol = vpart * (1.f / 64.f);

        // symmetry (x2: each flip-pair counted once per direction)
        const float loss_sym = 2.f * g_sym / 56623104.f;   // B*C*X^3

        if (c == 0)
            out[0] = 0.15f * loss_adj + 0.2f * loss_vol + 0.05f * loss_sym;

        // re-zero accumulators + counter for the next launch/replay
        __syncwarp();
        {
            float4 z = make_float4(0.f, 0.f, 0.f, 0.f);
            float4* za0 = reinterpret_cast<float4*>(&g_A[0][c * 32]);
            float4* za1 = reinterpret_cast<float4*>(&g_A[1][c * 32]);
            #pragma unroll
            for (int q = 0; q < 8; q++) { za0[q] = z; za1[q] = z; }
            g_vol[0][c] = 0.f;
            g_vol[1][c] = 0.f;
            if (c == 0) { g_sym = 0.f; g_done = 0u; }
        }
    }
}

extern "C" void kernel_launch(void* const* d_in, const int* in_sizes, int n_in,
                              void* d_out, int out_size) {
    const float* logits = (const float*)d_in[0];
    const float* age    = (const float*)d_in[1];
    const float* wy     = (const float*)d_in[2];
    const float* wo     = (const float*)d_in[3];
    const float* vmy    = (const float*)d_in[4];
    const float* vmo    = (const float*)d_in[5];
    const float* vsy    = (const float*)d_in[6];
    const float* vso    = (const float*)d_in[7];
    const float* prior  = (const float*)d_in[8];
    float* out = (float*)d_out;

    // Max shared-memory carveout so 13 blocks/SM (221KB aggregate) are resident.
    static bool attr_set = false;
    if (!attr_set) {
        cudaFuncSetAttribute(main_kernel,
                             cudaFuncAttributePreferredSharedMemoryCarveout, 100);
        attr_set = true;
    }

    main_kernel<<<GRID_TOTAL, 32>>>(logits, age, wy, wo, vmy, vmo, vsy, vso, prior, out);
}

// round 15
// speedup vs baseline: 1.6409x; 1.0715x over previous
#include <cuda_runtime.h>
#include <cuda_fp16.h>
#include <mma.h>

using namespace nvcuda;

// Problem constants (B=2, C=32, X=96)
#define BATCH        2
#define XD           96
#define XSTRIDE      9216        // 96*96
#define CH_STRIDE    884736      // X^3
#define B_STRIDE     28311552    // 32 * X^3
#define CHUNKS_PER_B 13824       // 48 * 288  (288 = 9216/32)
#define GPB          814         // blocks per batch; grid = 1628 = 11*148 (one wave at the
                                 // MEASURED 11 blocks/SM residency; 17 chunks/warp)
#define TILE_LD      72          // 64 voxels + 8 pad halves (fp16 tile, overlaid on stage)
#define STAGE_BYTES  8192        // 64 rows * 128B of staged logits per chunk
#define GRID_TOTAL   (BATCH * GPB)

// Accumulators: zero at module load; fused finalize re-zeroes after reading,
// so every launch/replay sees zeros (deterministic).
__device__ float    g_A[BATCH][1024];
__device__ float    g_vol[BATCH][32];
__device__ float    g_sym;
__device__ unsigned g_done;

__device__ __forceinline__ void cp_async16(void* smem_dst, const void* gmem_src) {
    unsigned saddr = (unsigned)__cvta_generic_to_shared(smem_dst);
    asm volatile("cp.async.cg.shared.global [%0], [%1], 16;\n"
                 :: "r"(saddr), "l"(gmem_src));
}
__device__ __forceinline__ void cp_commit() {
    asm volatile("cp.async.commit_group;\n");
}
template <int N>
__device__ __forceinline__ void cp_wait() {
    asm volatile("cp.async.wait_group %0;\n" :: "n"(N));
}

// Prefetch one chunk (64 rows x 128B) into a stage buffer. Always commits a
// group (possibly empty) so wait_group counting stays consistent.
__device__ __forceinline__ void prefetch_chunk(const float* __restrict__ Lb,
                                               unsigned chunk, char* stage,
                                               int lane, bool valid) {
    if (valid) {
        const unsigned x     = chunk / 288u;
        const unsigned sbase = (chunk - x * 288u) * 32u;
        const float* P1 = Lb + x * XSTRIDE + sbase;
        const float* P2 = Lb + (XD - 1 - x) * XSTRIDE + sbase;
        const int sub = lane >> 3;          // 0..3  (row group)
        const int off = (lane & 7) * 16;    // byte offset within 128B row
        #pragma unroll
        for (int k = 0; k < 8; k++) {
            int c = k * 4 + sub;
            cp_async16(stage + c * 128 + off,
                       (const char*)(P1 + c * CH_STRIDE) + off);
        }
        #pragma unroll
        for (int k = 0; k < 8; k++) {
            int c = k * 4 + sub;
            cp_async16(stage + (32 + c) * 128 + off,
                       (const char*)(P2 + c * CH_STRIDE) + off);
        }
    }
    cp_commit();
}

__global__ __launch_bounds__(32, 11) void main_kernel(
    const float* __restrict__ logits,
    const float* __restrict__ age,
    const float* __restrict__ wy,
    const float* __restrict__ wo,
    const float* __restrict__ vmy,
    const float* __restrict__ vmo,
    const float* __restrict__ vsy,
    const float* __restrict__ vso,
    const float* __restrict__ prior,
    float* __restrict__ out)
{
    __shared__ __align__(256) char stages[2][STAGE_BYTES];
    __shared__ __align__(256) __half ones_b[256];   // 16x16 col-major, col 0 = 1.0

    const int lane = threadIdx.x;                 // single warp per block
    const int b    = blockIdx.x / GPB;
    const int blk  = blockIdx.x % GPB;
    const unsigned wg    = blk;                   // warp id within batch
    const unsigned wstep = GPB;                   // 814 warps per batch

    // ones block: element (k,n) at ones_b[n*16+k]; column 0 = 1.0
    #pragma unroll
    for (int i = lane; i < 256; i += 32)
        ones_b[i] = (i < 16) ? __float2half(1.0f) : __float2half(0.0f);
    __syncwarp();

    const float* Lb = logits + b * B_STRIDE;

    wmma::fragment<wmma::accumulator, 16, 16, 16, float> acc[2][2];
    wmma::fragment<wmma::accumulator, 16, 16, 16, float> accv[2];
    #pragma unroll
    for (int i = 0; i < 2; i++) {
        wmma::fill_fragment(accv[i], 0.0f);
        #pragma unroll
        for (int j = 0; j < 2; j++)
            wmma::fill_fragment(acc[i][j], 0.0f);
    }
    wmma::fragment<wmma::matrix_b, 16, 16, 16, __half, wmma::col_major> fbv;
    wmma::load_matrix_sync(fbv, ones_b, 16);

    float symacc = 0.f;

    // ---- pipeline prologue: stage chunk(i) and chunk(i+wstep) ----
    prefetch_chunk(Lb, wg,          stages[0], lane, wg < CHUNKS_PER_B);
    prefetch_chunk(Lb, wg + wstep,  stages[1], lane, wg + wstep < CHUNKS_PER_B);

    unsigned parity = 0;
    for (unsigned chunk = wg; chunk < CHUNKS_PER_B; chunk += wstep) {
        cp_wait<1>();          // chunk's own stage group complete
        __syncwarp();

        char*  stage = stages[parity];
        const float* st = reinterpret_cast<const float*>(stage);
        __half* tile = reinterpret_cast<__half*>(stage);

        // softmax over 32 channels for voxel pair (l1 from rows 0..31, l2 rows 32..63).
        // No max-subtraction: logits ~N(0,1); h2exp cannot overflow half (needs >11).
        half2 h[32];
        #pragma unroll
        for (int c = 0; c < 32; c++)
            h[c] = h2exp(__floats2half2_rn(st[c * 32 + lane], st[(32 + c) * 32 + lane]));

        {
            half2 t[16];
            #pragma unroll
            for (int i = 0; i < 16; i++) t[i] = __hadd2(h[2 * i], h[2 * i + 1]);
            #pragma unroll
            for (int i = 0; i < 8; i++)  t[i] = __hadd2(t[i], t[i + 8]);
            #pragma unroll
            for (int i = 0; i < 4; i++)  t[i] = __hadd2(t[i], t[i + 4]);
            t[0] = __hadd2(t[0], t[2]);
            t[1] = __hadd2(t[1], t[3]);
            half2 inv = h2rcp(__hadd2(t[0], t[1]));
            #pragma unroll
            for (int c = 0; c < 32; c++) h[c] = __hmul2(h[c], inv);
        }

        // symmetry: pair (c, c+16): |p1[c]-p2[c+16]| + |p2[c]-p1[c+16]|
        {
            half2 sa = __floats2half2_rn(0.f, 0.f);
            #pragma unroll
            for (int i = 0; i < 16; i++) {
                half2 bs = __lowhigh2highlow(h[i + 16]);
                sa = __hadd2(sa, __habs2(__hsub2(h[i], bs)));
            }
            symacc += __low2float(sa) + __high2float(sa);
        }

        __syncwarp();   // all lanes done reading staged logits before tile overwrite

        // stage fp16 tile into the SAME buffer (4608B <= 8192B); pure K-permutation
        #pragma unroll
        for (int c = 0; c < 32; c++)
            *reinterpret_cast<half2*>(tile + c * TILE_LD + 2 * lane) = h[c];
        __syncwarp();

        // ---- Gram + volume accumulate on tensor pipe ----
        #pragma unroll
        for (int kk = 0; kk < 4; kk++) {
            wmma::fragment<wmma::matrix_a, 16, 16, 16, __half, wmma::row_major> fa0, fa1;
            wmma::fragment<wmma::matrix_b, 16, 16, 16, __half, wmma::col_major> fb0, fb1;
            wmma::load_matrix_sync(fa0, tile + kk * 16, TILE_LD);
            wmma::load_matrix_sync(fa1, tile + 16 * TILE_LD + kk * 16, TILE_LD);
            wmma::load_matrix_sync(fb0, tile + kk * 16, TILE_LD);
            wmma::load_matrix_sync(fb1, tile + 16 * TILE_LD + kk * 16, TILE_LD);
            wmma::mma_sync(acc[0][0], fa0, fb0, acc[0][0]);
            wmma::mma_sync(acc[0][1], fa0, fb1, acc[0][1]);
            wmma::mma_sync(acc[1][0], fa1, fb0, acc[1][0]);
            wmma::mma_sync(acc[1][1], fa1, fb1, acc[1][1]);
            wmma::mma_sync(accv[0], fa0, fbv, accv[0]);
            wmma::mma_sync(accv[1], fa1, fbv, accv[1]);
        }
        // tile reads complete (ldsm results in registers) -> safe to re-stage this buffer
        prefetch_chunk(Lb, chunk + 2 * wstep, stage, lane,
                       chunk + 2 * wstep < CHUNKS_PER_B);
        parity ^= 1;
    }

    cp_wait<0>();     // drain any in-flight (possibly empty) groups before buffer reuse
    __syncwarp();

    // ---- flush Gram: fragments -> smem (fp32, ld=32) -> global atomics ----
    float* ftile = reinterpret_cast<float*>(stages[0]);
    #pragma unroll
    for (int ci = 0; ci < 2; ci++)
        #pragma unroll
        for (int di = 0; di < 2; di++)
            wmma::store_matrix_sync(ftile + ci * 16 * 32 + di * 16, acc[ci][di], 32,
                                    wmma::mem_row_major);
    __syncwarp();
    #pragma unroll 4
    for (int r = 0; r < 32; r++)
        atomicAdd(&g_A[b][r * 32 + lane], ftile[r * 32 + lane]);
    __syncwarp();

    // ---- flush volume (column 0 of accv holds row sums) ----
    wmma::store_matrix_sync(ftile,       accv[0], 16, wmma::mem_row_major);
    wmma::store_matrix_sync(ftile + 256, accv[1], 16, wmma::mem_row_major);
    __syncwarp();
    {
        float v = (lane < 16) ? ftile[lane * 16] : ftile[256 + (lane - 16) * 16];
        atomicAdd(&g_vol[b][lane], v);
    }

    // ---- flush sym ----
    #pragma unroll
    for (int o = 16; o > 0; o >>= 1) symacc += __shfl_xor_sync(0xFFFFFFFF, symacc, o);
    if (lane == 0) atomicAdd(&g_sym, symacc);

    // ================= fused finalize: last block to finish =================
    __threadfence();
    __syncwarp();
    unsigned last = 0;
    if (lane == 0) last = (atomicAdd(&g_done, 1u) == GRID_TOTAL - 1) ? 1u : 0u;
    last = __shfl_sync(0xFFFFFFFF, last, 0);
    if (last) {
        __threadfence();
        const int c = lane;
        const float a0 = fminf(fmaxf(age[0] * 0.01f, 0.f), 1.f);
        const float a1 = fminf(fmaxf(age[1] * 0.01f, 0.f), 1.f);

        // batched row loads (float4, high MLP)
        float4 A0[8], A1[8], WY[8], WO[8], PR[8];
        {
            const float4* a0p = reinterpret_cast<const float4*>(&g_A[0][c * 32]);
            const float4* a1p = reinterpret_cast<const float4*>(&g_A[1][c * 32]);
            const float4* wyp = reinterpret_cast<const float4*>(wy + c * 32);
            const float4* wop = reinterpret_cast<const float4*>(wo + c * 32);
            const float4* prp = reinterpret_cast<const float4*>(prior + c * 32);
            #pragma unroll
            for (int q = 0; q < 8; q++) A0[q] = a0p[q];
            #pragma unroll
            for (int q = 0; q < 8; q++) A1[q] = a1p[q];
            #pragma unroll
            for (int q = 0; q < 8; q++) WY[q] = wyp[q];
            #pragma unroll
            for (int q = 0; q < 8; q++) WO[q] = wop[q];
            #pragma unroll
            for (int q = 0; q < 8; q++) PR[q] = prp[q];
        }
        const float* a0f = reinterpret_cast<const float*>(A0);
        const float* a1f = reinterpret_cast<const float*>(A1);
        const float* wyf = reinterpret_cast<const float*>(WY);
        const float* wof = reinterpret_cast<const float*>(WO);
        const float* prf = reinterpret_cast<const float*>(PR);

        float aw[32], pr[32];
        float rsum = 0.f, psum = 0.f;
        #pragma unroll
        for (int d = 0; d < 32; d++) {
            float w0 = (1.f - a0) * wyf[d] + a0 * wof[d];
            float w1 = (1.f - a1) * wyf[d] + a1 * wof[d];
            float v = (d == c) ? 0.f : 0.5f * (a0f[d] * w0 + a1f[d] * w1);
            aw[d] = v; rsum += v;
            float pv = (d == c) ? 0.f : prf[d];
            pr[d] = pv; psum += pv;
        }
        const float rinv = 1.f / fmaxf(rsum, 1e-8f);
        const float pinv = 1.f / fmaxf(psum, 1e-8f);
        float part = 0.f;
        #pragma unroll
        for (int d = 0; d < 32; d++) part += fabsf(aw[d] * rinv - pr[d] * pinv);
        #pragma unroll
        for (int o = 16; o > 0; o >>= 1) part += __shfl_xor_sync(0xFFFFFFFF, part, o);
        const float loss_adj = part * (1.f / 1024.f);

        // volume smooth-L1
        float vpart = 0.f;
        {
            float mean = (1.f - a0) * vmy[c] + a0 * vmo[c];
            float std  = (1.f - a0) * vsy[c] + a0 * vso[c];
            float xx = (g_vol[0][c] - mean) / (std + 1e-6f);
            float ax = fabsf(xx);
            vpart += (ax < 1.f) ? 0.5f * xx * xx : ax - 0.5f;
        }
        {
            float mean = (1.f - a1) * vmy[c] + a1 * vmo[c];
            float std  = (1.f - a1) * vsy[c] + a1 * vso[c];
            float xx = (g_vol[1][c] - mean) / (std + 1e-6f);
            float ax = fabsf(xx);
            vpart += (ax < 1.f) ? 0.5f * xx * xx : ax - 0.5f;
        }
        #pragma unroll
        for (int o = 16; o > 0; o >>= 1) vpart += __shfl_xor_sync(0xFFFFFFFF, vpart, o);
        const float loss_vol = vpart * (1.f / 64.f);

        // symmetry (x2: each flip-pair counted once per direction)
        const float loss_sym = 2.f * g_sym / 56623104.f;   // B*C*X^3

        if (c == 0)
            out[0] = 0.15f * loss_adj + 0.2f * loss_vol + 0.05f * loss_sym;

        // re-zero accumulators + counter for the next launch/replay
        __syncwarp();
        {
            float4 z = make_float4(0.f, 0.f, 0.f, 0.f);
            float4* za0 = reinterpret_cast<float4*>(&g_A[0][c * 32]);
            float4* za1 = reinterpret_cast<float4*>(&g_A[1][c * 32]);
            #pragma unroll
            for (int q = 0; q < 8; q++) { za0[q] = z; za1[q] = z; }
            g_vol[0][c] = 0.f;
            g_vol[1][c] = 0.f;
            if (c == 0) { g_sym = 0.f; g_done = 0u; }
        }
    }
}

extern "C" void kernel_launch(void* const* d_in, const int* in_sizes, int n_in,
                              void* d_out, int out_size) {
    const float* logits = (const float*)d_in[0];
    const float* age    = (const float*)d_in[1];
    const float* wy     = (const float*)d_in[2];
    const float* wo     = (const float*)d_in[3];
    const float* vmy    = (const float*)d_in[4];
    const float* vmo    = (const float*)d_in[5];
    const float* vsy    = (const float*)d_in[6];
    const float* vso    = (const float*)d_in[7];
    const float* prior  = (const float*)d_in[8];
    float* out = (float*)d_out;

    // Prefer max shared-memory carveout (hint; harmless if ignored).
    static bool attr_set = false;
    if (!attr_set) {
        cudaFuncSetAttribute(main_kernel,
                             cudaFuncAttributePreferredSharedMemoryCarveout, 100);
        attr_set = true;
    }

    main_kernel<<<GRID_TOTAL, 32>>>(logits, age, wy, wo, vmy, vmo, vsy, vso, prior, out);
}